// round 11
// baseline (speedup 1.0000x reference)
#include <cuda_runtime.h>
#include <cuda_fp16.h>

typedef unsigned int u32;
#define DEVINL __device__ __forceinline__

static constexpr int Bb = 8, Ll = 2048, Dd = 64;
static constexpr int TQ = 128, NT = 512, NTILES = 16;
static constexpr int NSTAGE = 4;
static constexpr float QSCALE = 0.18033688011112042f; // log2(e)/8

// global scratch: fp16, tile-swizzled, contiguous 16KB per tile
__device__ __align__(16) unsigned char g_q[Bb][16][16384];
__device__ __align__(16) unsigned char g_k[Bb][16][16384];
__device__ __align__(16) unsigned char g_v[Bb][16][16384];

// smem layout
static constexpr int OF_K = 0;            // within a 32KB stage
static constexpr int OF_V = 16384;
static constexpr int STAGESZ = 32768;     // 4 stages: 0..131071
static constexpr int SM_Q  = 131072;      // fp16 [128][64] = 16KB
static constexpr int SM_KM = 147456;      // 2048 f32 = 8KB (whole batch row of KM)
static constexpr int SM_BAR = 155648;     // full[4] then empty[4], 8B each
static constexpr int SM_TOT = 155776;

DEVINL u32 smem_u32(const void* p) {
    u32 a;
    asm("{ .reg .u64 t; cvta.to.shared.u64 t, %1; cvt.u32.u64 %0, t; }" : "=r"(a) : "l"(p));
    return a;
}
DEVINL u32 swz(u32 o) { return o ^ ((o >> 3) & 0x70); }
DEVINL float ex2f(float x) { float r; asm("ex2.approx.f32 %0, %1;" : "=f"(r) : "f"(x)); return r; }
DEVINL u32 packh2(float lo, float hi) {
    u32 r; asm("cvt.rn.f16x2.f32 %0, %1, %2;" : "=r"(r) : "f"(hi), "f"(lo)); return r;
}

DEVINL void ldsm4(u32* r, u32 a) {
    asm volatile("ldmatrix.sync.aligned.m8n8.x4.shared.b16 {%0,%1,%2,%3}, [%4];"
                 : "=r"(r[0]), "=r"(r[1]), "=r"(r[2]), "=r"(r[3]) : "r"(a) : "memory");
}
DEVINL void ldsm4t(u32* r, u32 a) {
    asm volatile("ldmatrix.sync.aligned.m8n8.x4.trans.shared.b16 {%0,%1,%2,%3}, [%4];"
                 : "=r"(r[0]), "=r"(r[1]), "=r"(r[2]), "=r"(r[3]) : "r"(a) : "memory");
}
DEVINL void mma16816(float* c, const u32* a, u32 b0, u32 b1) {
    asm("mma.sync.aligned.m16n8k16.row.col.f32.f16.f16.f32 "
        "{%0,%1,%2,%3}, {%4,%5,%6,%7}, {%8,%9}, {%0,%1,%2,%3};"
        : "+f"(c[0]), "+f"(c[1]), "+f"(c[2]), "+f"(c[3])
        : "r"(a[0]), "r"(a[1]), "r"(a[2]), "r"(a[3]), "r"(b0), "r"(b1));
}

DEVINL void cpa16(u32 dst, const void* src) {
    asm volatile("cp.async.cg.shared.global [%0], [%1], 16;" :: "r"(dst), "l"(src) : "memory");
}
DEVINL void cpa_commit() { asm volatile("cp.async.commit_group;" ::: "memory"); }
DEVINL void cpa_wait0()  { asm volatile("cp.async.wait_group 0;" ::: "memory"); }

// ---- mbarrier / bulk-copy primitives (sm_90 PTX; no 'a' features) ----
DEVINL void mbar_init(u32 bar, u32 cnt) {
    asm volatile("mbarrier.init.shared.b64 [%0], %1;" :: "r"(bar), "r"(cnt) : "memory");
}
DEVINL void mbar_arrive(u32 bar) {
    asm volatile("mbarrier.arrive.shared.b64 _, [%0];" :: "r"(bar) : "memory");
}
DEVINL void mbar_expect_tx(u32 bar, u32 bytes) {
    asm volatile("mbarrier.arrive.expect_tx.shared.b64 _, [%0], %1;"
                 :: "r"(bar), "r"(bytes) : "memory");
}
DEVINL void mbar_wait(u32 bar, u32 parity) {
    asm volatile(
        "{\n\t.reg .pred P;\n\t"
        "WL_%=:\n\t"
        "mbarrier.try_wait.parity.acquire.cta.shared::cta.b64 P, [%0], %1, 0x989680;\n\t"
        "@P bra WD_%=;\n\t"
        "bra WL_%=;\n\t"
        "WD_%=:\n\t}"
        :: "r"(bar), "r"(parity) : "memory");
}
DEVINL void bulk_cp(u32 dst, const void* src, u32 bar) {
    asm volatile(
        "cp.async.bulk.shared::cta.global.mbarrier::complete_tx::bytes [%0], [%1], %2, [%3];"
        :: "r"(dst), "l"(src), "r"(16384u), "r"(bar) : "memory");
}

// ---------------- kernel 1: fp32 -> fp16, tile-swizzled ----------------
__global__ void __launch_bounds__(256, 4)
presplit(const float* __restrict__ Q, const float* __restrict__ K,
         const float* __restrict__ V)
{
    int tensor = blockIdx.y;                       // 0=K, 1=V, 2=Q(scaled)
    int c = blockIdx.x * 256 + threadIdx.x;
    int b  = c >> 14;
    int l  = (c >> 3) & 2047;
    int d0 = (c & 7) * 8;

    const float* src = (tensor == 0 ? K : tensor == 1 ? V : Q)
                       + ((size_t)(b * Ll + l) * Dd + d0);
    float4 a = *reinterpret_cast<const float4*>(src);
    float4 e = *reinterpret_cast<const float4*>(src + 4);
    if (tensor == 2) {
        a.x *= QSCALE; a.y *= QSCALE; a.z *= QSCALE; a.w *= QSCALE;
        e.x *= QSCALE; e.y *= QSCALE; e.z *= QSCALE; e.w *= QSCALE;
    }
    uint4 H = make_uint4(packh2(a.x, a.y), packh2(a.z, a.w),
                         packh2(e.x, e.y), packh2(e.z, e.w));
    int tile = l >> 7, row = l & 127;
    u32 off = swz((u32)(row * 128 + d0 * 2));
    unsigned char* oh = (tensor == 0 ? g_k : tensor == 1 ? g_v : g_q)[b][tile];
    *reinterpret_cast<uint4*>(oh + off) = H;
}

// ---------------- kernel 2: attention, mbarrier-pipelined ----------------
__global__ void __launch_bounds__(NT, 1)
attn_mma(const float* __restrict__ QM, const float* __restrict__ KM,
         float* __restrict__ Out)
{
    extern __shared__ char sm[];
    const u32 smb = smem_u32(sm);
    const int tid = threadIdx.x, w = tid >> 5, L = tid & 31;
    const int b = blockIdx.y, qt = blockIdx.x, q0 = qt * TQ;
    const int mg = w >> 2, kq = w & 3;   // 4 row-groups x 4 key-quarters

    // init: Q (16KB) + km (8KB whole batch) via per-thread cp.async; barriers
    {
        u32 o = (u32)tid * 16;
        cpa16(smb + SM_Q + o, g_q[b][qt] + o * 2 / 2);            // 512*16 = 8KB... two rounds:
        cpa16(smb + SM_Q + 8192 + o, g_q[b][qt] + 8192 + o);
        cpa16(smb + SM_KM + o, KM + b * Ll + tid * 4);
        // fix first Q round address (tid*16 straightforward)
        cpa_commit();
        if (tid == 0) {
#pragma unroll
            for (int s = 0; s < NSTAGE; ++s) {
                mbar_init(smb + SM_BAR + s * 8, 1);        // full
                mbar_init(smb + SM_BAR + 32 + s * 8, 16);  // empty: 16 warps
            }
        }
        cpa_wait0();
        __syncthreads();
    }

    // producer prologue: issue stages 0..2
    if (tid == 0) {
#pragma unroll
        for (int it = 0; it < 3; ++it) {
            u32 s = (u32)it & 3;
            u32 fb = smb + SM_BAR + s * 8;
            mbar_wait(smb + SM_BAR + 32 + s * 8, 1u);      // fresh -> immediate
            mbar_expect_tx(fb, 32768u);
            bulk_cp(smb + s * STAGESZ + OF_K, g_k[b][it], fb);
            bulk_cp(smb + s * STAGESZ + OF_V, g_v[b][it], fb);
        }
    }

    // lane addressing (invariant registers)
    const int m = L >> 3;
    const u32 xm = (u32)(L & 7) << 4;
    const int arw = (m & 1) * 8 + (L & 7);
    const u32 acolsel = (u32)(m >> 1) * 16;
    const u32 krw_off = (u32)((m >> 1) * 8 + (L & 7)) * 128;
    const u32 kcolsel = (u32)(m & 1) * 16;
    const u32 vrw_off = (u32)arw * 128;
    const u32 vcolsel = (u32)(m >> 1) * 16;
    const u32 kqrow = (u32)(kq * 32);

    u32 qaddr[4][2], koff[4], voff[4];
#pragma unroll
    for (int kc = 0; kc < 4; ++kc) {
        u32 qcoff = (((u32)kc * 32 + acolsel) ^ xm);
        qaddr[kc][0] = smb + SM_Q + (u32)(mg * 32 + arw) * 128 + qcoff;
        qaddr[kc][1] = smb + SM_Q + (u32)(mg * 32 + 16 + arw) * 128 + qcoff;
        koff[kc] = OF_K + kqrow * 128 + krw_off + (((u32)kc * 32 + kcolsel) ^ xm);
        voff[kc] = OF_V + kqrow * 128 + vrw_off + (((u32)kc * 32 + vcolsel) ^ xm);
    }
    const float* km_base = reinterpret_cast<const float*>(sm + SM_KM) + kq * 32 + 2 * (L & 3);

    float oacc[2][8][4];
#pragma unroll
    for (int mt = 0; mt < 2; ++mt)
#pragma unroll
        for (int j = 0; j < 8; ++j)
            { oacc[mt][j][0] = 0; oacc[mt][j][1] = 0; oacc[mt][j][2] = 0; oacc[mt][j][3] = 0; }
    float rs[2][2] = {{0.f, 0.f}, {0.f, 0.f}};

    for (int kt = 0; kt < NTILES; ++kt) {
        const u32 s = (u32)kt & 3;
        const u32 sbase = smb + s * STAGESZ;
        const u32 parity = ((u32)kt >> 2) & 1u;
        mbar_wait(smb + SM_BAR + s * 8, parity);

        // ---- GEMM1: S[32 rows][32 keys] = Q @ K^T ----
        float sacc[2][4][4];
#pragma unroll
        for (int mt = 0; mt < 2; ++mt)
#pragma unroll
            for (int j = 0; j < 4; ++j)
                { sacc[mt][j][0] = 0; sacc[mt][j][1] = 0; sacc[mt][j][2] = 0; sacc[mt][j][3] = 0; }
#pragma unroll
        for (int kc = 0; kc < 4; ++kc) {
            u32 qh0[4], qh1[4];
            ldsm4(qh0, qaddr[kc][0]);
            ldsm4(qh1, qaddr[kc][1]);
#pragma unroll
            for (int j2 = 0; j2 < 2; ++j2) {
                u32 bh[4];
                ldsm4(bh, sbase + koff[kc] + (u32)j2 * 2048);
                mma16816(sacc[0][2 * j2],     qh0, bh[0], bh[1]);
                mma16816(sacc[0][2 * j2 + 1], qh0, bh[2], bh[3]);
                mma16816(sacc[1][2 * j2],     qh1, bh[0], bh[1]);
                mma16816(sacc[1][2 * j2 + 1], qh1, bh[2], bh[3]);
            }
        }

        // ---- softmax + GEMM2: O += P @ V ----
        const float* kmp = km_base + kt * 128;
#pragma unroll
        for (int kc = 0; kc < 2; ++kc) {
            u32 Ah[2][4];
#pragma unroll
            for (int mt = 0; mt < 2; ++mt)
#pragma unroll
                for (int half = 0; half < 2; ++half) {
                    int j = 2 * kc + half;
                    float2 km2 = *reinterpret_cast<const float2*>(kmp + 8 * j);
                    float p0 = ex2f(sacc[mt][j][0]) * km2.x;
                    float p1 = ex2f(sacc[mt][j][1]) * km2.y;
                    float p2 = ex2f(sacc[mt][j][2]) * km2.x;
                    float p3 = ex2f(sacc[mt][j][3]) * km2.y;
                    rs[mt][0] += p0 + p1;
                    rs[mt][1] += p2 + p3;
                    Ah[mt][2 * half]     = packh2(p0, p1);
                    Ah[mt][2 * half + 1] = packh2(p2, p3);
                }
#pragma unroll
            for (int j2 = 0; j2 < 4; ++j2) {
                u32 vh[4];
                ldsm4t(vh, sbase + voff[j2] + (u32)kc * 2048);
                mma16816(oacc[0][2 * j2],     Ah[0], vh[0], vh[1]);
                mma16816(oacc[0][2 * j2 + 1], Ah[0], vh[2], vh[3]);
                mma16816(oacc[1][2 * j2],     Ah[1], vh[0], vh[1]);
                mma16816(oacc[1][2 * j2 + 1], Ah[1], vh[2], vh[3]);
            }
        }

        // done reading stage s
        if (L == 0) mbar_arrive(smb + SM_BAR + 32 + s * 8);

        // producer: issue tile kt+3
        if (tid == 0 && kt + 3 < NTILES) {
            const int it = kt + 3;
            u32 s2 = (u32)it & 3;
            u32 fb = smb + SM_BAR + s2 * 8;
            mbar_wait(smb + SM_BAR + 32 + s2 * 8, ((((u32)it >> 2) & 1u) ^ 1u));
            mbar_expect_tx(fb, 32768u);
            bulk_cp(smb + s2 * STAGESZ + OF_K, g_k[b][it], fb);
            bulk_cp(smb + s2 * STAGESZ + OF_V, g_v[b][it], fb);
        }
    }

    // ---- epilogue: quad-reduce rowsums, 4-way key-quarter combine ----
#pragma unroll
    for (int mt = 0; mt < 2; ++mt)
#pragma unroll
        for (int sdx = 0; sdx < 2; ++sdx) {
            rs[mt][sdx] += __shfl_xor_sync(0xFFFFFFFFu, rs[mt][sdx], 1);
            rs[mt][sdx] += __shfl_xor_sync(0xFFFFFFFFu, rs[mt][sdx], 2);
        }
    __syncthreads();   // pipeline fully drained; smem stages reusable

    float* OS = reinterpret_cast<float*>(sm);            // 3 x [128][64] f32
    float* RS = reinterpret_cast<float*>(sm + 98304);    // 3 x [128]
    if (kq != 0) {
        const int ib = kq - 1;
#pragma unroll
        for (int mt = 0; mt < 2; ++mt) {
            int ra = mg * 32 + mt * 16 + (L >> 2);
            int rb = ra + 8;
#pragma unroll
            for (int j = 0; j < 8; ++j) {
                *reinterpret_cast<float2*>(&OS[ib * 8192 + ra * 64 + 8 * j + 2 * (L & 3)]) =
                    make_float2(oacc[mt][j][0], oacc[mt][j][1]);
                *reinterpret_cast<float2*>(&OS[ib * 8192 + rb * 64 + 8 * j + 2 * (L & 3)]) =
                    make_float2(oacc[mt][j][2], oacc[mt][j][3]);
            }
            if ((L & 3) == 0) { RS[ib * 128 + ra] = rs[mt][0]; RS[ib * 128 + rb] = rs[mt][1]; }
        }
    }
    __syncthreads();
    if (kq == 0) {
#pragma unroll
        for (int mt = 0; mt < 2; ++mt) {
            int ra = mg * 32 + mt * 16 + (L >> 2);
            int rb = ra + 8;
            float sa = rs[mt][0] + RS[ra] + RS[128 + ra] + RS[256 + ra];
            float sb = rs[mt][1] + RS[rb] + RS[128 + rb] + RS[256 + rb];
            float dva = QM[b * Ll + q0 + ra] / fmaxf(sa, 2e-15f);
            float dvb = QM[b * Ll + q0 + rb] / fmaxf(sb, 2e-15f);
            float* oa = Out + (size_t)(b * Ll + q0 + ra) * Dd + 2 * (L & 3);
            float* ob = Out + (size_t)(b * Ll + q0 + rb) * Dd + 2 * (L & 3);
#pragma unroll
            for (int j = 0; j < 8; ++j) {
                int ca = ra * 64 + 8 * j + 2 * (L & 3);
                int cb = rb * 64 + 8 * j + 2 * (L & 3);
                float2 u0 = *reinterpret_cast<const float2*>(&OS[ca]);
                float2 u1 = *reinterpret_cast<const float2*>(&OS[8192 + ca]);
                float2 u2 = *reinterpret_cast<const float2*>(&OS[16384 + ca]);
                float2 v0 = *reinterpret_cast<const float2*>(&OS[cb]);
                float2 v1 = *reinterpret_cast<const float2*>(&OS[8192 + cb]);
                float2 v2 = *reinterpret_cast<const float2*>(&OS[16384 + cb]);
                *reinterpret_cast<float2*>(oa + 8 * j) =
                    make_float2((oacc[mt][j][0] + u0.x + u1.x + u2.x) * dva,
                                (oacc[mt][j][1] + u0.y + u1.y + u2.y) * dva);
                *reinterpret_cast<float2*>(ob + 8 * j) =
                    make_float2((oacc[mt][j][2] + v0.x + v1.x + v2.x) * dvb,
                                (oacc[mt][j][3] + v0.y + v1.y + v2.y) * dvb);
            }
        }
    }
}

extern "C" void kernel_launch(void* const* d_in, const int* in_sizes, int n_in,
                              void* d_out, int out_size) {
    const float* Q  = (const float*)d_in[0];
    const float* K  = (const float*)d_in[1];
    const float* V  = (const float*)d_in[2];
    const float* QM = (const float*)d_in[3];
    const float* KM = (const float*)d_in[4];
    float* Out = (float*)d_out;

    presplit<<<dim3(512, 3), 256>>>(Q, K, V);

    cudaFuncSetAttribute(attn_mma, cudaFuncAttributeMaxDynamicSharedMemorySize, SM_TOT);
    dim3 grid(Ll / TQ, Bb);   // 16 q-tiles x 8 batches = 128 CTAs, 1 per SM
    attn_mma<<<grid, NT, SM_TOT>>>(QM, KM, Out);
}

// round 12
// speedup vs baseline: 1.0531x; 1.0531x over previous
#include <cuda_runtime.h>
#include <cuda_fp16.h>

typedef unsigned int u32;
#define DEVINL __device__ __forceinline__

static constexpr int Bb = 8, Ll = 2048, Dd = 64;
static constexpr int TQ = 128, NT = 512, NTILES = 16;
static constexpr int NSTAGE = 4;
static constexpr float QSCALE = 0.18033688011112042f; // log2(e)/8

// scratch: per tile one contiguous blob: K(16KB swz) | km*V(16KB swz) | kmcol(2KB) pad to 36KB
static constexpr int OF_K = 0;
static constexpr int OF_V = 16384;
static constexpr int OF_M = 32768;
static constexpr int TILEB = 36864;
__device__ __align__(16) unsigned char g_kv[Bb][16][TILEB];
__device__ __align__(16) unsigned char g_q[Bb][16][16384];

// smem layout
static constexpr int STAGESZ = TILEB;          // 4 stages: 0..147455
static constexpr int SM_Q   = 147456;          // fp16 [128][64] = 16KB
static constexpr int SM_BAR = 163840;          // full[4] @ +0, empty[4] @ +32
static constexpr int SM_TOT = 163968;

DEVINL u32 smem_u32(const void* p) {
    u32 a;
    asm("{ .reg .u64 t; cvta.to.shared.u64 t, %1; cvt.u32.u64 %0, t; }" : "=r"(a) : "l"(p));
    return a;
}
DEVINL u32 swz(u32 o) { return o ^ ((o >> 3) & 0x70); }
DEVINL float ex2f(float x) { float r; asm("ex2.approx.f32 %0, %1;" : "=f"(r) : "f"(x)); return r; }
DEVINL u32 packh2(float lo, float hi) {
    u32 r; asm("cvt.rn.f16x2.f32 %0, %1, %2;" : "=r"(r) : "f"(hi), "f"(lo)); return r;
}

DEVINL void ldsm4(u32* r, u32 a) {
    asm volatile("ldmatrix.sync.aligned.m8n8.x4.shared.b16 {%0,%1,%2,%3}, [%4];"
                 : "=r"(r[0]), "=r"(r[1]), "=r"(r[2]), "=r"(r[3]) : "r"(a) : "memory");
}
DEVINL void ldsm4t(u32* r, u32 a) {
    asm volatile("ldmatrix.sync.aligned.m8n8.x4.trans.shared.b16 {%0,%1,%2,%3}, [%4];"
                 : "=r"(r[0]), "=r"(r[1]), "=r"(r[2]), "=r"(r[3]) : "r"(a) : "memory");
}
DEVINL void ldsm2t(u32* r, u32 a) {
    asm volatile("ldmatrix.sync.aligned.m8n8.x2.trans.shared.b16 {%0,%1}, [%2];"
                 : "=r"(r[0]), "=r"(r[1]) : "r"(a) : "memory");
}
DEVINL void mma16816(float* c, const u32* a, u32 b0, u32 b1) {
    asm("mma.sync.aligned.m16n8k16.row.col.f32.f16.f16.f32 "
        "{%0,%1,%2,%3}, {%4,%5,%6,%7}, {%8,%9}, {%0,%1,%2,%3};"
        : "+f"(c[0]), "+f"(c[1]), "+f"(c[2]), "+f"(c[3])
        : "r"(a[0]), "r"(a[1]), "r"(a[2]), "r"(a[3]), "r"(b0), "r"(b1));
}

DEVINL void cpa16(u32 dst, const void* src) {
    asm volatile("cp.async.cg.shared.global [%0], [%1], 16;" :: "r"(dst), "l"(src) : "memory");
}
DEVINL void cpa_commit() { asm volatile("cp.async.commit_group;" ::: "memory"); }
DEVINL void cpa_wait0()  { asm volatile("cp.async.wait_group 0;" ::: "memory"); }

DEVINL void mbar_init(u32 bar, u32 cnt) {
    asm volatile("mbarrier.init.shared.b64 [%0], %1;" :: "r"(bar), "r"(cnt) : "memory");
}
DEVINL void mbar_arrive(u32 bar) {
    asm volatile("mbarrier.arrive.shared.b64 _, [%0];" :: "r"(bar) : "memory");
}
DEVINL void mbar_expect_tx(u32 bar, u32 bytes) {
    asm volatile("mbarrier.arrive.expect_tx.shared.b64 _, [%0], %1;"
                 :: "r"(bar), "r"(bytes) : "memory");
}
DEVINL void mbar_wait(u32 bar, u32 parity) {
    asm volatile(
        "{\n\t.reg .pred P;\n\t"
        "WL_%=:\n\t"
        "mbarrier.try_wait.parity.acquire.cta.shared::cta.b64 P, [%0], %1, 0x989680;\n\t"
        "@P bra WD_%=;\n\t"
        "bra WL_%=;\n\t"
        "WD_%=:\n\t}"
        :: "r"(bar), "r"(parity) : "memory");
}
DEVINL void bulk_cp(u32 dst, const void* src, u32 bytes, u32 bar) {
    asm volatile(
        "cp.async.bulk.shared::cta.global.mbarrier::complete_tx::bytes [%0], [%1], %2, [%3];"
        :: "r"(dst), "l"(src), "r"(bytes), "r"(bar) : "memory");
}

// ---------------- kernel 1: fp32 -> fp16, tile-swizzled; V masked; km column ----------------
__global__ void __launch_bounds__(256, 4)
presplit(const float* __restrict__ Q, const float* __restrict__ K,
         const float* __restrict__ V, const float* __restrict__ KM)
{
    int tensor = blockIdx.y;                       // 0=K, 1=V(masked)+kmcol, 2=Q(scaled)
    int c = blockIdx.x * 256 + threadIdx.x;
    int b  = c >> 14;
    int l  = (c >> 3) & 2047;
    int d0 = (c & 7) * 8;

    const float* src = (tensor == 0 ? K : tensor == 1 ? V : Q)
                       + ((size_t)(b * Ll + l) * Dd + d0);
    float4 a = *reinterpret_cast<const float4*>(src);
    float4 e = *reinterpret_cast<const float4*>(src + 4);
    float scl = (tensor == 2) ? QSCALE : 1.0f;
    float km = 0.f;
    if (tensor == 1) { km = KM[b * Ll + l]; scl = km; }
    if (tensor != 0) {
        a.x *= scl; a.y *= scl; a.z *= scl; a.w *= scl;
        e.x *= scl; e.y *= scl; e.z *= scl; e.w *= scl;
    }
    uint4 H = make_uint4(packh2(a.x, a.y), packh2(a.z, a.w),
                         packh2(e.x, e.y), packh2(e.z, e.w));
    int tile = l >> 7, row = l & 127;
    u32 off = swz((u32)(row * 128 + d0 * 2));
    unsigned char* dstp;
    if (tensor == 2)      dstp = g_q[b][tile];
    else if (tensor == 0) dstp = g_kv[b][tile] + OF_K;
    else                  dstp = g_kv[b][tile] + OF_V;
    *reinterpret_cast<uint4*>(dstp + off) = H;
    if (tensor == 1 && d0 == 0) {
        // km column tile: [128 rows][8 half cols], col0 = km, rest 0
        *reinterpret_cast<uint4*>(g_kv[b][tile] + OF_M + row * 16) =
            make_uint4(packh2(km, 0.f), 0u, 0u, 0u);
    }
}

// ---------------- kernel 2: attention, mbarrier-pipelined ----------------
__global__ void __launch_bounds__(NT, 1)
attn_mma(const float* __restrict__ QM, float* __restrict__ Out)
{
    extern __shared__ char sm[];
    const u32 smb = smem_u32(sm);
    const int tid = threadIdx.x, w = tid >> 5, L = tid & 31;
    const int b = blockIdx.y, qt = blockIdx.x, q0 = qt * TQ;
    const int mg = w >> 2, kq = w & 3;   // 4 row-groups x 4 key-quarters

    // init: Q (16KB) via cp.async; barriers
    {
        u32 o = (u32)tid * 16;
        cpa16(smb + SM_Q + o, g_q[b][qt] + o);
        cpa16(smb + SM_Q + 8192 + o, g_q[b][qt] + 8192 + o);
        cpa_commit();
        if (tid == 0) {
#pragma unroll
            for (int s = 0; s < NSTAGE; ++s) {
                mbar_init(smb + SM_BAR + s * 8, 1);        // full
                mbar_init(smb + SM_BAR + 32 + s * 8, 16);  // empty: 16 warps
            }
        }
        cpa_wait0();
        __syncthreads();
    }

    // producer prologue: stages 0..2
    if (tid == 0) {
#pragma unroll
        for (int it = 0; it < 3; ++it) {
            u32 s = (u32)it & 3;
            u32 fb = smb + SM_BAR + s * 8;
            mbar_wait(smb + SM_BAR + 32 + s * 8, 1u);
            mbar_expect_tx(fb, (u32)TILEB);
            bulk_cp(smb + s * STAGESZ, g_kv[b][it], (u32)TILEB, fb);
        }
    }

    // lane addressing (invariant registers)
    const int m = L >> 3;
    const u32 xm = (u32)(L & 7) << 4;
    const int arw = (m & 1) * 8 + (L & 7);
    const u32 acolsel = (u32)(m >> 1) * 16;
    const u32 krw_off = (u32)((m >> 1) * 8 + (L & 7)) * 128;
    const u32 kcolsel = (u32)(m & 1) * 16;
    const u32 vrw_off = (u32)arw * 128;
    const u32 vcolsel = (u32)(m >> 1) * 16;
    const u32 kqrow = (u32)(kq * 32);

    u32 qaddr[4][2], koff[4], voff[4];
#pragma unroll
    for (int kc = 0; kc < 4; ++kc) {
        u32 qcoff = (((u32)kc * 32 + acolsel) ^ xm);
        qaddr[kc][0] = smb + SM_Q + (u32)(mg * 32 + arw) * 128 + qcoff;
        qaddr[kc][1] = smb + SM_Q + (u32)(mg * 32 + 16 + arw) * 128 + qcoff;
        koff[kc] = OF_K + kqrow * 128 + krw_off + (((u32)kc * 32 + kcolsel) ^ xm);
        voff[kc] = OF_V + kqrow * 128 + vrw_off + (((u32)kc * 32 + vcolsel) ^ xm);
    }
    // km-column tile row address (16B rows, lanes 0-15 used by ldsm2t)
    const u32 moff0 = OF_M + (kqrow + (u32)arw) * 16;

    float oacc[2][8][4];
    float oaccE[2][4];   // extra n8 tile: col 64 = rowsum
#pragma unroll
    for (int mt = 0; mt < 2; ++mt) {
#pragma unroll
        for (int j = 0; j < 8; ++j)
            { oacc[mt][j][0] = 0; oacc[mt][j][1] = 0; oacc[mt][j][2] = 0; oacc[mt][j][3] = 0; }
        oaccE[mt][0] = 0; oaccE[mt][1] = 0; oaccE[mt][2] = 0; oaccE[mt][3] = 0;
    }

    for (int kt = 0; kt < NTILES; ++kt) {
        const u32 s = (u32)kt & 3;
        const u32 sbase = smb + s * STAGESZ;
        mbar_wait(smb + SM_BAR + s * 8, ((u32)kt >> 2) & 1u);

        // ---- GEMM1: S[32 rows][32 keys] = Q @ K^T ----
        float sacc[2][4][4];
#pragma unroll
        for (int mt = 0; mt < 2; ++mt)
#pragma unroll
            for (int j = 0; j < 4; ++j)
                { sacc[mt][j][0] = 0; sacc[mt][j][1] = 0; sacc[mt][j][2] = 0; sacc[mt][j][3] = 0; }
#pragma unroll
        for (int kc = 0; kc < 4; ++kc) {
            u32 qh0[4], qh1[4];
            ldsm4(qh0, qaddr[kc][0]);
            ldsm4(qh1, qaddr[kc][1]);
#pragma unroll
            for (int j2 = 0; j2 < 2; ++j2) {
                u32 bh[4];
                ldsm4(bh, sbase + koff[kc] + (u32)j2 * 2048);
                mma16816(sacc[0][2 * j2],     qh0, bh[0], bh[1]);
                mma16816(sacc[0][2 * j2 + 1], qh0, bh[2], bh[3]);
                mma16816(sacc[1][2 * j2],     qh1, bh[0], bh[1]);
                mma16816(sacc[1][2 * j2 + 1], qh1, bh[2], bh[3]);
            }
        }

        // ---- softmax (exp only) + GEMM2: O += P @ (km*V), rowsum via km column ----
#pragma unroll
        for (int kc = 0; kc < 2; ++kc) {
            u32 Ah[2][4];
#pragma unroll
            for (int mt = 0; mt < 2; ++mt)
#pragma unroll
                for (int half = 0; half < 2; ++half) {
                    int j = 2 * kc + half;
                    float p0 = ex2f(sacc[mt][j][0]);
                    float p1 = ex2f(sacc[mt][j][1]);
                    float p2 = ex2f(sacc[mt][j][2]);
                    float p3 = ex2f(sacc[mt][j][3]);
                    Ah[mt][2 * half]     = packh2(p0, p1);
                    Ah[mt][2 * half + 1] = packh2(p2, p3);
                }
            u32 bm[2];
            ldsm2t(bm, sbase + moff0 + (u32)kc * 256);   // 16 rows * 16B
            mma16816(oaccE[0], Ah[0], bm[0], bm[1]);
            mma16816(oaccE[1], Ah[1], bm[0], bm[1]);
#pragma unroll
            for (int j2 = 0; j2 < 4; ++j2) {
                u32 vh[4];
                ldsm4t(vh, sbase + voff[j2] + (u32)kc * 2048);
                mma16816(oacc[0][2 * j2],     Ah[0], vh[0], vh[1]);
                mma16816(oacc[0][2 * j2 + 1], Ah[0], vh[2], vh[3]);
                mma16816(oacc[1][2 * j2],     Ah[1], vh[0], vh[1]);
                mma16816(oacc[1][2 * j2 + 1], Ah[1], vh[2], vh[3]);
            }
        }

        if (L == 0) mbar_arrive(smb + SM_BAR + 32 + s * 8);

        if (tid == 0 && kt + 3 < NTILES) {
            const int it = kt + 3;
            u32 s2 = (u32)it & 3;
            u32 fb = smb + SM_BAR + s2 * 8;
            mbar_wait(smb + SM_BAR + 32 + s2 * 8, ((((u32)it >> 2) & 1u) ^ 1u));
            mbar_expect_tx(fb, (u32)TILEB);
            bulk_cp(smb + s2 * STAGESZ, g_kv[b][it], (u32)TILEB, fb);
        }
    }

    // ---- epilogue ----
    // rowsum = col 64 of extra tile: held at (L&3)==0 in oaccE[mt][0] (row L>>2) / [2] (row+8)
    float rsA[2], rsB[2];
#pragma unroll
    for (int mt = 0; mt < 2; ++mt) {
        rsA[mt] = __shfl_sync(0xFFFFFFFFu, oaccE[mt][0], L & ~3);
        rsB[mt] = __shfl_sync(0xFFFFFFFFu, oaccE[mt][2], L & ~3);
    }
    __syncthreads();   // pipeline drained; stage smem reusable

    float* OS = reinterpret_cast<float*>(sm);            // 3 x [128][64] f32
    float* RS = reinterpret_cast<float*>(sm + 98304);    // 3 x [128]
    if (kq != 0) {
        const int ib = kq - 1;
#pragma unroll
        for (int mt = 0; mt < 2; ++mt) {
            int ra = mg * 32 + mt * 16 + (L >> 2);
            int rb = ra + 8;
#pragma unroll
            for (int j = 0; j < 8; ++j) {
                *reinterpret_cast<float2*>(&OS[ib * 8192 + ra * 64 + 8 * j + 2 * (L & 3)]) =
                    make_float2(oacc[mt][j][0], oacc[mt][j][1]);
                *reinterpret_cast<float2*>(&OS[ib * 8192 + rb * 64 + 8 * j + 2 * (L & 3)]) =
                    make_float2(oacc[mt][j][2], oacc[mt][j][3]);
            }
            if ((L & 3) == 0) { RS[ib * 128 + ra] = rsA[mt]; RS[ib * 128 + rb] = rsB[mt]; }
        }
    }
    __syncthreads();
    if (kq == 0) {
#pragma unroll
        for (int mt = 0; mt < 2; ++mt) {
            int ra = mg * 32 + mt * 16 + (L >> 2);
            int rb = ra + 8;
            float sa = rsA[mt] + RS[ra] + RS[128 + ra] + RS[256 + ra];
            float sb = rsB[mt] + RS[rb] + RS[128 + rb] + RS[256 + rb];
            float dva = QM[b * Ll + q0 + ra] / fmaxf(sa, 2e-15f);
            float dvb = QM[b * Ll + q0 + rb] / fmaxf(sb, 2e-15f);
            float* oa = Out + (size_t)(b * Ll + q0 + ra) * Dd + 2 * (L & 3);
            float* ob = Out + (size_t)(b * Ll + q0 + rb) * Dd + 2 * (L & 3);
#pragma unroll
            for (int j = 0; j < 8; ++j) {
                int ca = ra * 64 + 8 * j + 2 * (L & 3);
                int cb = rb * 64 + 8 * j + 2 * (L & 3);
                float2 u0 = *reinterpret_cast<const float2*>(&OS[ca]);
                float2 u1 = *reinterpret_cast<const float2*>(&OS[8192 + ca]);
                float2 u2 = *reinterpret_cast<const float2*>(&OS[16384 + ca]);
                float2 v0 = *reinterpret_cast<const float2*>(&OS[cb]);
                float2 v1 = *reinterpret_cast<const float2*>(&OS[8192 + cb]);
                float2 v2 = *reinterpret_cast<const float2*>(&OS[16384 + cb]);
                *reinterpret_cast<float2*>(oa + 8 * j) =
                    make_float2((oacc[mt][j][0] + u0.x + u1.x + u2.x) * dva,
                                (oacc[mt][j][1] + u0.y + u1.y + u2.y) * dva);
                *reinterpret_cast<float2*>(ob + 8 * j) =
                    make_float2((oacc[mt][j][2] + v0.x + v1.x + v2.x) * dvb,
                                (oacc[mt][j][3] + v0.y + v1.y + v2.y) * dvb);
            }
        }
    }
}

extern "C" void kernel_launch(void* const* d_in, const int* in_sizes, int n_in,
                              void* d_out, int out_size) {
    const float* Q  = (const float*)d_in[0];
    const float* K  = (const float*)d_in[1];
    const float* V  = (const float*)d_in[2];
    const float* QM = (const float*)d_in[3];
    const float* KM = (const float*)d_in[4];
    float* Out = (float*)d_out;

    presplit<<<dim3(512, 3), 256>>>(Q, K, V, KM);

    cudaFuncSetAttribute(attn_mma, cudaFuncAttributeMaxDynamicSharedMemorySize, SM_TOT);
    dim3 grid(Ll / TQ, Bb);   // 16 q-tiles x 8 batches = 128 CTAs, 1 per SM
    attn_mma<<<grid, NT, SM_TOT>>>(QM, Out);
}

// round 13
// speedup vs baseline: 1.0539x; 1.0008x over previous
#include <cuda_runtime.h>
#include <cuda_fp16.h>

typedef unsigned int u32;
#define DEVINL __device__ __forceinline__

static constexpr int Bb = 8, Ll = 2048, Dd = 64;
static constexpr int TQ = 128, NT = 512, NTILES = 16;
static constexpr int NSTAGE = 4;
static constexpr float QSCALE = 0.18033688011112042f; // log2(e)/8

// scratch: per tile one contiguous blob: K(16KB swz) | km*V(16KB swz) | kmcol(2KB) pad to 36KB
static constexpr int OF_K = 0;
static constexpr int OF_V = 16384;
static constexpr int OF_M = 32768;
static constexpr int TILEB = 36864;
__device__ __align__(16) unsigned char g_kv[Bb][16][TILEB];
__device__ __align__(16) unsigned char g_q[Bb][16][16384];

// smem layout
static constexpr int STAGESZ = TILEB;          // 4 stages: 0..147455
static constexpr int SM_Q   = 147456;          // fp16 [128][64] = 16KB
static constexpr int SM_BAR = 163840;          // full[4] @ +0, empty[4] @ +32
static constexpr int SM_TOT = 163968;

DEVINL u32 smem_u32(const void* p) {
    u32 a;
    asm("{ .reg .u64 t; cvta.to.shared.u64 t, %1; cvt.u32.u64 %0, t; }" : "=r"(a) : "l"(p));
    return a;
}
DEVINL u32 swz(u32 o) { return o ^ ((o >> 3) & 0x70); }
DEVINL float ex2f(float x) { float r; asm("ex2.approx.f32 %0, %1;" : "=f"(r) : "f"(x)); return r; }
DEVINL u32 packh2(float lo, float hi) {
    u32 r; asm("cvt.rn.f16x2.f32 %0, %1, %2;" : "=r"(r) : "f"(hi), "f"(lo)); return r;
}

DEVINL void ldsm4(u32* r, u32 a) {
    asm volatile("ldmatrix.sync.aligned.m8n8.x4.shared.b16 {%0,%1,%2,%3}, [%4];"
                 : "=r"(r[0]), "=r"(r[1]), "=r"(r[2]), "=r"(r[3]) : "r"(a) : "memory");
}
DEVINL void ldsm4t(u32* r, u32 a) {
    asm volatile("ldmatrix.sync.aligned.m8n8.x4.trans.shared.b16 {%0,%1,%2,%3}, [%4];"
                 : "=r"(r[0]), "=r"(r[1]), "=r"(r[2]), "=r"(r[3]) : "r"(a) : "memory");
}
DEVINL void ldsm2t(u32* r, u32 a) {
    asm volatile("ldmatrix.sync.aligned.m8n8.x2.trans.shared.b16 {%0,%1}, [%2];"
                 : "=r"(r[0]), "=r"(r[1]) : "r"(a) : "memory");
}
DEVINL void mma16816(float* c, const u32* a, u32 b0, u32 b1) {
    asm("mma.sync.aligned.m16n8k16.row.col.f32.f16.f16.f32 "
        "{%0,%1,%2,%3}, {%4,%5,%6,%7}, {%8,%9}, {%0,%1,%2,%3};"
        : "+f"(c[0]), "+f"(c[1]), "+f"(c[2]), "+f"(c[3])
        : "r"(a[0]), "r"(a[1]), "r"(a[2]), "r"(a[3]), "r"(b0), "r"(b1));
}

DEVINL void cpa16(u32 dst, const void* src) {
    asm volatile("cp.async.cg.shared.global [%0], [%1], 16;" :: "r"(dst), "l"(src) : "memory");
}
DEVINL void cpa_commit() { asm volatile("cp.async.commit_group;" ::: "memory"); }
DEVINL void cpa_wait0()  { asm volatile("cp.async.wait_group 0;" ::: "memory"); }

DEVINL void mbar_init(u32 bar, u32 cnt) {
    asm volatile("mbarrier.init.shared.b64 [%0], %1;" :: "r"(bar), "r"(cnt) : "memory");
}
DEVINL void mbar_arrive(u32 bar) {
    asm volatile("mbarrier.arrive.shared.b64 _, [%0];" :: "r"(bar) : "memory");
}
DEVINL void mbar_expect_tx(u32 bar, u32 bytes) {
    asm volatile("mbarrier.arrive.expect_tx.shared.b64 _, [%0], %1;"
                 :: "r"(bar), "r"(bytes) : "memory");
}
DEVINL void mbar_wait(u32 bar, u32 parity) {
    asm volatile(
        "{\n\t.reg .pred P;\n\t"
        "WL_%=:\n\t"
        "mbarrier.try_wait.parity.acquire.cta.shared::cta.b64 P, [%0], %1, 0x989680;\n\t"
        "@P bra WD_%=;\n\t"
        "bra WL_%=;\n\t"
        "WD_%=:\n\t}"
        :: "r"(bar), "r"(parity) : "memory");
}
DEVINL void bulk_cp(u32 dst, const void* src, u32 bytes, u32 bar) {
    asm volatile(
        "cp.async.bulk.shared::cta.global.mbarrier::complete_tx::bytes [%0], [%1], %2, [%3];"
        :: "r"(dst), "l"(src), "r"(bytes), "r"(bar) : "memory");
}

// ---------------- kernel 1: fp32 -> fp16, tile-swizzled; V masked; km column ----------------
__global__ void __launch_bounds__(256, 4)
presplit(const float* __restrict__ Q, const float* __restrict__ K,
         const float* __restrict__ V, const float* __restrict__ KM)
{
    int tensor = blockIdx.y;                       // 0=K, 1=V(masked)+kmcol, 2=Q(scaled)
    int c = blockIdx.x * 256 + threadIdx.x;
    int b  = c >> 14;
    int l  = (c >> 3) & 2047;
    int d0 = (c & 7) * 8;

    const float* src = (tensor == 0 ? K : tensor == 1 ? V : Q)
                       + ((size_t)(b * Ll + l) * Dd + d0);
    float4 a = *reinterpret_cast<const float4*>(src);
    float4 e = *reinterpret_cast<const float4*>(src + 4);
    float scl = (tensor == 2) ? QSCALE : 1.0f;
    float km = 0.f;
    if (tensor == 1) { km = KM[b * Ll + l]; scl = km; }
    if (tensor != 0) {
        a.x *= scl; a.y *= scl; a.z *= scl; a.w *= scl;
        e.x *= scl; e.y *= scl; e.z *= scl; e.w *= scl;
    }
    uint4 H = make_uint4(packh2(a.x, a.y), packh2(a.z, a.w),
                         packh2(e.x, e.y), packh2(e.z, e.w));
    int tile = l >> 7, row = l & 127;
    u32 off = swz((u32)(row * 128 + d0 * 2));
    unsigned char* dstp;
    if (tensor == 2)      dstp = g_q[b][tile];
    else if (tensor == 0) dstp = g_kv[b][tile] + OF_K;
    else                  dstp = g_kv[b][tile] + OF_V;
    *reinterpret_cast<uint4*>(dstp + off) = H;
    if (tensor == 1 && d0 == 0) {
        // km column tile: [128 rows][8 half cols], col0 = km, rest 0
        *reinterpret_cast<uint4*>(g_kv[b][tile] + OF_M + row * 16) =
            make_uint4(packh2(km, 0.f), 0u, 0u, 0u);
    }
}

// ---------------- kernel 2: attention, mbarrier-pipelined, key-half split ----------------
__global__ void __launch_bounds__(NT, 1)
attn_mma(const float* __restrict__ QM, float* __restrict__ Out)
{
    extern __shared__ char sm[];
    const u32 smb = smem_u32(sm);
    const int tid = threadIdx.x, w = tid >> 5, L = tid & 31;
    const int b = blockIdx.y, qt = blockIdx.x, q0 = qt * TQ;
    const int mg = w >> 2, kq = w & 3;   // 4 row-groups x 4 key-quarters

    // init: Q (16KB) via cp.async; barriers
    {
        u32 o = (u32)tid * 16;
        cpa16(smb + SM_Q + o, g_q[b][qt] + o);
        cpa16(smb + SM_Q + 8192 + o, g_q[b][qt] + 8192 + o);
        cpa_commit();
        if (tid == 0) {
#pragma unroll
            for (int s = 0; s < NSTAGE; ++s) {
                mbar_init(smb + SM_BAR + s * 8, 1);        // full
                mbar_init(smb + SM_BAR + 32 + s * 8, 16);  // empty: 16 warps
            }
        }
        cpa_wait0();
        __syncthreads();
    }

    // producer prologue: stages 0..2
    if (tid == 0) {
#pragma unroll
        for (int it = 0; it < 3; ++it) {
            u32 s = (u32)it & 3;
            u32 fb = smb + SM_BAR + s * 8;
            mbar_wait(smb + SM_BAR + 32 + s * 8, 1u);
            mbar_expect_tx(fb, (u32)TILEB);
            bulk_cp(smb + s * STAGESZ, g_kv[b][it], (u32)TILEB, fb);
        }
    }

    // lane addressing — compact register set
    const int m = L >> 3;
    const u32 xm = (u32)(L & 7) << 4;
    const int arw = (m & 1) * 8 + (L & 7);
    const u32 acolsel = (u32)(m >> 1) * 16;
    const u32 kcolsel = (u32)(m & 1) * 16;
    const u32 vcolsel = acolsel;
    const u32 kqrow = (u32)(kq * 32);

    const u32 qbase = smb + SM_Q + (u32)(mg * 32 + arw) * 128;   // +2048 for m-tile 1
    u32 qcoff[4], koff[4], voff[4];
#pragma unroll
    for (int kc = 0; kc < 4; ++kc) {
        qcoff[kc] = (((u32)kc * 32 + acolsel) ^ xm);
        koff[kc] = OF_K + kqrow * 128 + (u32)((m >> 1) * 8 + (L & 7)) * 128
                 + (((u32)kc * 32 + kcolsel) ^ xm);
        voff[kc] = OF_V + kqrow * 128 + (u32)arw * 128
                 + (((u32)kc * 32 + vcolsel) ^ xm);
    }
    const u32 moff0 = OF_M + (kqrow + (u32)arw) * 16;

    float oacc[2][8][4];
    float oaccE[2][4];   // extra n8 tile: col 64 = rowsum
#pragma unroll
    for (int mt = 0; mt < 2; ++mt) {
#pragma unroll
        for (int j = 0; j < 8; ++j)
            { oacc[mt][j][0] = 0; oacc[mt][j][1] = 0; oacc[mt][j][2] = 0; oacc[mt][j][3] = 0; }
        oaccE[mt][0] = 0; oaccE[mt][1] = 0; oaccE[mt][2] = 0; oaccE[mt][3] = 0;
    }

    for (int kt = 0; kt < NTILES; ++kt) {
        const u32 s = (u32)kt & 3;
        const u32 sbase = smb + s * STAGESZ;
        mbar_wait(smb + SM_BAR + s * 8, ((u32)kt >> 2) & 1u);

#pragma unroll
        for (int h = 0; h < 2; ++h) {
            const u32 hoff = (u32)h * 2048;

            // ---- GEMM1 half: S[32 rows][16 keys] ----
            float sacc[2][2][4];
#pragma unroll
            for (int mt = 0; mt < 2; ++mt)
#pragma unroll
                for (int j = 0; j < 2; ++j)
                    { sacc[mt][j][0] = 0; sacc[mt][j][1] = 0; sacc[mt][j][2] = 0; sacc[mt][j][3] = 0; }
#pragma unroll
            for (int kc = 0; kc < 4; ++kc) {
                u32 qh0[4], qh1[4], bh[4];
                ldsm4(qh0, qbase + qcoff[kc]);
                ldsm4(qh1, qbase + 2048 + qcoff[kc]);
                ldsm4(bh, sbase + koff[kc] + hoff);
                mma16816(sacc[0][0], qh0, bh[0], bh[1]);
                mma16816(sacc[0][1], qh0, bh[2], bh[3]);
                mma16816(sacc[1][0], qh1, bh[0], bh[1]);
                mma16816(sacc[1][1], qh1, bh[2], bh[3]);
            }

            // ---- softmax (exp only) -> A fragments ----
            u32 Ah[2][4];
#pragma unroll
            for (int mt = 0; mt < 2; ++mt)
#pragma unroll
                for (int j = 0; j < 2; ++j) {
                    float p0 = ex2f(sacc[mt][j][0]);
                    float p1 = ex2f(sacc[mt][j][1]);
                    float p2 = ex2f(sacc[mt][j][2]);
                    float p3 = ex2f(sacc[mt][j][3]);
                    Ah[mt][2 * j]     = packh2(p0, p1);
                    Ah[mt][2 * j + 1] = packh2(p2, p3);
                }

            // ---- rowsum via km-column MMA ----
            {
                u32 bm[2];
                ldsm2t(bm, sbase + moff0 + (u32)h * 256);
                mma16816(oaccE[0], Ah[0], bm[0], bm[1]);
                mma16816(oaccE[1], Ah[1], bm[0], bm[1]);
            }

            // ---- GEMM2 half: O += P @ (km*V) ----
#pragma unroll
            for (int j2 = 0; j2 < 4; ++j2) {
                u32 vh[4];
                ldsm4t(vh, sbase + voff[j2] + hoff);
                mma16816(oacc[0][2 * j2],     Ah[0], vh[0], vh[1]);
                mma16816(oacc[0][2 * j2 + 1], Ah[0], vh[2], vh[3]);
                mma16816(oacc[1][2 * j2],     Ah[1], vh[0], vh[1]);
                mma16816(oacc[1][2 * j2 + 1], Ah[1], vh[2], vh[3]);
            }
        }

        if (L == 0) mbar_arrive(smb + SM_BAR + 32 + s * 8);

        if (tid == 0 && kt + 3 < NTILES) {
            const int it = kt + 3;
            u32 s2 = (u32)it & 3;
            u32 fb = smb + SM_BAR + s2 * 8;
            mbar_wait(smb + SM_BAR + 32 + s2 * 8, ((((u32)it >> 2) & 1u) ^ 1u));
            mbar_expect_tx(fb, (u32)TILEB);
            bulk_cp(smb + s2 * STAGESZ, g_kv[b][it], (u32)TILEB, fb);
        }
    }

    // ---- epilogue ----
    float rsA[2], rsB[2];
#pragma unroll
    for (int mt = 0; mt < 2; ++mt) {
        rsA[mt] = __shfl_sync(0xFFFFFFFFu, oaccE[mt][0], L & ~3);
        rsB[mt] = __shfl_sync(0xFFFFFFFFu, oaccE[mt][2], L & ~3);
    }
    __syncthreads();   // pipeline drained; stage smem reusable

    float* OS = reinterpret_cast<float*>(sm);            // 3 x [128][64] f32
    float* RS = reinterpret_cast<float*>(sm + 98304);    // 3 x [128]
    if (kq != 0) {
        const int ib = kq - 1;
#pragma unroll
        for (int mt = 0; mt < 2; ++mt) {
            int ra = mg * 32 + mt * 16 + (L >> 2);
            int rb = ra + 8;
#pragma unroll
            for (int j = 0; j < 8; ++j) {
                *reinterpret_cast<float2*>(&OS[ib * 8192 + ra * 64 + 8 * j + 2 * (L & 3)]) =
                    make_float2(oacc[mt][j][0], oacc[mt][j][1]);
                *reinterpret_cast<float2*>(&OS[ib * 8192 + rb * 64 + 8 * j + 2 * (L & 3)]) =
                    make_float2(oacc[mt][j][2], oacc[mt][j][3]);
            }
            if ((L & 3) == 0) { RS[ib * 128 + ra] = rsA[mt]; RS[ib * 128 + rb] = rsB[mt]; }
        }
    }
    __syncthreads();
    if (kq == 0) {
#pragma unroll
        for (int mt = 0; mt < 2; ++mt) {
            int ra = mg * 32 + mt * 16 + (L >> 2);
            int rb = ra + 8;
            float sa = rsA[mt] + RS[ra] + RS[128 + ra] + RS[256 + ra];
            float sb = rsB[mt] + RS[rb] + RS[128 + rb] + RS[256 + rb];
            float dva = QM[b * Ll + q0 + ra] / fmaxf(sa, 2e-15f);
            float dvb = QM[b * Ll + q0 + rb] / fmaxf(sb, 2e-15f);
            float* oa = Out + (size_t)(b * Ll + q0 + ra) * Dd + 2 * (L & 3);
            float* ob = Out + (size_t)(b * Ll + q0 + rb) * Dd + 2 * (L & 3);
#pragma unroll
            for (int j = 0; j < 8; ++j) {
                int ca = ra * 64 + 8 * j + 2 * (L & 3);
                int cb = rb * 64 + 8 * j + 2 * (L & 3);
                float2 u0 = *reinterpret_cast<const float2*>(&OS[ca]);
                float2 u1 = *reinterpret_cast<const float2*>(&OS[8192 + ca]);
                float2 u2 = *reinterpret_cast<const float2*>(&OS[16384 + ca]);
                float2 v0 = *reinterpret_cast<const float2*>(&OS[cb]);
                float2 v1 = *reinterpret_cast<const float2*>(&OS[8192 + cb]);
                float2 v2 = *reinterpret_cast<const float2*>(&OS[16384 + cb]);
                *reinterpret_cast<float2*>(oa + 8 * j) =
                    make_float2((oacc[mt][j][0] + u0.x + u1.x + u2.x) * dva,
                                (oacc[mt][j][1] + u0.y + u1.y + u2.y) * dva);
                *reinterpret_cast<float2*>(ob + 8 * j) =
                    make_float2((oacc[mt][j][2] + v0.x + v1.x + v2.x) * dvb,
                                (oacc[mt][j][3] + v0.y + v1.y + v2.y) * dvb);
            }
        }
    }
}

extern "C" void kernel_launch(void* const* d_in, const int* in_sizes, int n_in,
                              void* d_out, int out_size) {
    const float* Q  = (const float*)d_in[0];
    const float* K  = (const float*)d_in[1];
    const float* V  = (const float*)d_in[2];
    const float* QM = (const float*)d_in[3];
    const float* KM = (const float*)d_in[4];
    float* Out = (float*)d_out;

    presplit<<<dim3(512, 3), 256>>>(Q, K, V, KM);

    cudaFuncSetAttribute(attn_mma, cudaFuncAttributeMaxDynamicSharedMemorySize, SM_TOT);
    dim3 grid(Ll / TQ, Bb);   // 16 q-tiles x 8 batches = 128 CTAs, 1 per SM
    attn_mma<<<grid, NT, SM_TOT>>>(QM, Out);
}

// round 14
// speedup vs baseline: 1.3072x; 1.2403x over previous
#include <cuda_runtime.h>
#include <cuda_fp16.h>

typedef unsigned int u32;
#define DEVINL __device__ __forceinline__

static constexpr int Bb = 8, Ll = 2048, Dd = 64;
static constexpr int TQ = 128, NT = 256, NTILES = 16;
static constexpr int NSTAGE = 4;
static constexpr float QSCALE = 0.18033688011112042f; // log2(e)/8

// scratch: per tile one contiguous blob: K(16KB swz) | km*V(16KB swz) | kmcol(2KB) pad to 36KB
static constexpr int OF_K = 0;
static constexpr int OF_V = 16384;
static constexpr int OF_M = 32768;
static constexpr int TILEB = 36864;
__device__ __align__(16) unsigned char g_kv[Bb][16][TILEB];
__device__ __align__(16) unsigned char g_q[Bb][16][16384];

// smem layout
static constexpr int STAGESZ = TILEB;          // 4 stages: 0..147455
static constexpr int SM_Q   = 147456;          // fp16 [128][64] = 16KB
static constexpr int SM_BAR = 163840;          // full[4] @ +0, empty[4] @ +32
static constexpr int SM_TOT = 163968;

DEVINL u32 smem_u32(const void* p) {
    u32 a;
    asm("{ .reg .u64 t; cvta.to.shared.u64 t, %1; cvt.u32.u64 %0, t; }" : "=r"(a) : "l"(p));
    return a;
}
DEVINL u32 swz(u32 o) { return o ^ ((o >> 3) & 0x70); }
DEVINL float ex2f(float x) { float r; asm("ex2.approx.f32 %0, %1;" : "=f"(r) : "f"(x)); return r; }
DEVINL u32 packh2(float lo, float hi) {
    u32 r; asm("cvt.rn.f16x2.f32 %0, %1, %2;" : "=r"(r) : "f"(hi), "f"(lo)); return r;
}

DEVINL void ldsm4(u32* r, u32 a) {
    asm volatile("ldmatrix.sync.aligned.m8n8.x4.shared.b16 {%0,%1,%2,%3}, [%4];"
                 : "=r"(r[0]), "=r"(r[1]), "=r"(r[2]), "=r"(r[3]) : "r"(a) : "memory");
}
DEVINL void ldsm4t(u32* r, u32 a) {
    asm volatile("ldmatrix.sync.aligned.m8n8.x4.trans.shared.b16 {%0,%1,%2,%3}, [%4];"
                 : "=r"(r[0]), "=r"(r[1]), "=r"(r[2]), "=r"(r[3]) : "r"(a) : "memory");
}
DEVINL void ldsm2t(u32* r, u32 a) {
    asm volatile("ldmatrix.sync.aligned.m8n8.x2.trans.shared.b16 {%0,%1}, [%2];"
                 : "=r"(r[0]), "=r"(r[1]) : "r"(a) : "memory");
}
DEVINL void mma16816(float* c, const u32* a, u32 b0, u32 b1) {
    asm("mma.sync.aligned.m16n8k16.row.col.f32.f16.f16.f32 "
        "{%0,%1,%2,%3}, {%4,%5,%6,%7}, {%8,%9}, {%0,%1,%2,%3};"
        : "+f"(c[0]), "+f"(c[1]), "+f"(c[2]), "+f"(c[3])
        : "r"(a[0]), "r"(a[1]), "r"(a[2]), "r"(a[3]), "r"(b0), "r"(b1));
}

DEVINL void cpa16(u32 dst, const void* src) {
    asm volatile("cp.async.cg.shared.global [%0], [%1], 16;" :: "r"(dst), "l"(src) : "memory");
}
DEVINL void cpa_commit() { asm volatile("cp.async.commit_group;" ::: "memory"); }
DEVINL void cpa_wait0()  { asm volatile("cp.async.wait_group 0;" ::: "memory"); }

DEVINL void mbar_init(u32 bar, u32 cnt) {
    asm volatile("mbarrier.init.shared.b64 [%0], %1;" :: "r"(bar), "r"(cnt) : "memory");
}
DEVINL void mbar_arrive(u32 bar) {
    asm volatile("mbarrier.arrive.shared.b64 _, [%0];" :: "r"(bar) : "memory");
}
DEVINL void mbar_expect_tx(u32 bar, u32 bytes) {
    asm volatile("mbarrier.arrive.expect_tx.shared.b64 _, [%0], %1;"
                 :: "r"(bar), "r"(bytes) : "memory");
}
DEVINL void mbar_wait(u32 bar, u32 parity) {
    asm volatile(
        "{\n\t.reg .pred P;\n\t"
        "WL_%=:\n\t"
        "mbarrier.try_wait.parity.acquire.cta.shared::cta.b64 P, [%0], %1, 0x989680;\n\t"
        "@P bra WD_%=;\n\t"
        "bra WL_%=;\n\t"
        "WD_%=:\n\t}"
        :: "r"(bar), "r"(parity) : "memory");
}
DEVINL void bulk_cp(u32 dst, const void* src, u32 bytes, u32 bar) {
    asm volatile(
        "cp.async.bulk.shared::cta.global.mbarrier::complete_tx::bytes [%0], [%1], %2, [%3];"
        :: "r"(dst), "l"(src), "r"(bytes), "r"(bar) : "memory");
}

// ---------------- kernel 1: fp32 -> fp16, tile-swizzled; V masked; km column ----------------
__global__ void __launch_bounds__(256, 4)
presplit(const float* __restrict__ Q, const float* __restrict__ K,
         const float* __restrict__ V, const float* __restrict__ KM)
{
    int tensor = blockIdx.y;                       // 0=K, 1=V(masked)+kmcol, 2=Q(scaled)
    int c = blockIdx.x * 256 + threadIdx.x;
    int b  = c >> 14;
    int l  = (c >> 3) & 2047;
    int d0 = (c & 7) * 8;

    const float* src = (tensor == 0 ? K : tensor == 1 ? V : Q)
                       + ((size_t)(b * Ll + l) * Dd + d0);
    float4 a = *reinterpret_cast<const float4*>(src);
    float4 e = *reinterpret_cast<const float4*>(src + 4);
    float scl = (tensor == 2) ? QSCALE : 1.0f;
    float km = 0.f;
    if (tensor == 1) { km = KM[b * Ll + l]; scl = km; }
    if (tensor != 0) {
        a.x *= scl; a.y *= scl; a.z *= scl; a.w *= scl;
        e.x *= scl; e.y *= scl; e.z *= scl; e.w *= scl;
    }
    uint4 H = make_uint4(packh2(a.x, a.y), packh2(a.z, a.w),
                         packh2(e.x, e.y), packh2(e.z, e.w));
    int tile = l >> 7, row = l & 127;
    u32 off = swz((u32)(row * 128 + d0 * 2));
    unsigned char* dstp;
    if (tensor == 2)      dstp = g_q[b][tile];
    else if (tensor == 0) dstp = g_kv[b][tile] + OF_K;
    else                  dstp = g_kv[b][tile] + OF_V;
    *reinterpret_cast<uint4*>(dstp + off) = H;
    if (tensor == 1 && d0 == 0) {
        // km column tile: [128 rows][8 half cols], col0 = km, rest 0
        *reinterpret_cast<uint4*>(g_kv[b][tile] + OF_M + row * 16) =
            make_uint4(packh2(km, 0.f), 0u, 0u, 0u);
    }
}

// ---------------- kernel 2: attention; 8 warps, Q resident, chunk-interleaved ----------------
__global__ void __launch_bounds__(NT, 1)
attn_mma(const float* __restrict__ QM, float* __restrict__ Out)
{
    extern __shared__ char sm[];
    const u32 smb = smem_u32(sm);
    const int tid = threadIdx.x, w = tid >> 5, L = tid & 31;
    const int b = blockIdx.y, qt = blockIdx.x, q0 = qt * TQ;
    const int mg = w >> 1, kh = w & 1;   // 4 row-groups x 2 key-halves

    // init: Q (16KB) via cp.async; barriers
    {
#pragma unroll
        for (int r = 0; r < 4; ++r) {
            u32 o = (u32)tid * 16 + (u32)r * 4096;
            cpa16(smb + SM_Q + o, g_q[b][qt] + o);
        }
        cpa_commit();
        if (tid == 0) {
#pragma unroll
            for (int s = 0; s < NSTAGE; ++s) {
                mbar_init(smb + SM_BAR + s * 8, 1);        // full
                mbar_init(smb + SM_BAR + 32 + s * 8, 8);   // empty: 8 warps
            }
        }
        cpa_wait0();
        __syncthreads();
    }

    // producer prologue: stages 0..2
    if (tid == 0) {
#pragma unroll
        for (int it = 0; it < 3; ++it) {
            u32 s = (u32)it & 3;
            u32 fb = smb + SM_BAR + s * 8;
            mbar_wait(smb + SM_BAR + 32 + s * 8, 1u);
            mbar_expect_tx(fb, (u32)TILEB);
            bulk_cp(smb + s * STAGESZ, g_kv[b][it], (u32)TILEB, fb);
        }
    }

    // lane addressing
    const int m = L >> 3;
    const u32 xm = (u32)(L & 7) << 4;
    const int arw = (m & 1) * 8 + (L & 7);

    // Q fragments: register-resident (2 m-tiles x 4 k-chunks)
    u32 qf[2][4][4];
#pragma unroll
    for (int mt = 0; mt < 2; ++mt)
#pragma unroll
        for (int kc = 0; kc < 4; ++kc)
            ldsm4(qf[mt][kc],
                  smb + SM_Q + (u32)(mg * 32 + mt * 16 + arw) * 128
                  + (((u32)kc * 32 + (u32)(m >> 1) * 16) ^ xm));

    u32 koff[4], voff[4];
#pragma unroll
    for (int i = 0; i < 4; ++i) {
        koff[i] = OF_K + (u32)kh * 8192 + (u32)((m >> 1) * 8 + (L & 7)) * 128
                + (((u32)i * 32 + (u32)(m & 1) * 16) ^ xm);
        voff[i] = OF_V + (u32)kh * 8192 + (u32)arw * 128
                + (((u32)i * 32 + (u32)(m >> 1) * 16) ^ xm);
    }
    const u32 moff0 = OF_M + (u32)kh * 1024 + (u32)arw * 16;

    float oacc[2][8][4];
    float oaccE[2][4];   // extra n8 tile: col 64 = rowsum
#pragma unroll
    for (int mt = 0; mt < 2; ++mt) {
#pragma unroll
        for (int j = 0; j < 8; ++j)
            { oacc[mt][j][0] = 0; oacc[mt][j][1] = 0; oacc[mt][j][2] = 0; oacc[mt][j][3] = 0; }
        oaccE[mt][0] = 0; oaccE[mt][1] = 0; oaccE[mt][2] = 0; oaccE[mt][3] = 0;
    }

    for (int kt = 0; kt < NTILES; ++kt) {
        const u32 s = (u32)kt & 3;
        const u32 sbase = smb + s * STAGESZ;
        mbar_wait(smb + SM_BAR + s * 8, ((u32)kt >> 2) & 1u);

        // 4 chunks of 16 keys; fine-grained G1 -> exp -> G2 interleave
#pragma unroll
        for (int c = 0; c < 4; ++c) {
            const u32 coff = (u32)c * 2048;

            // ---- GEMM1 chunk: S[32 rows][16 keys] ----
            float sacc[2][2][4];
#pragma unroll
            for (int mt = 0; mt < 2; ++mt)
#pragma unroll
                for (int j = 0; j < 2; ++j)
                    { sacc[mt][j][0] = 0; sacc[mt][j][1] = 0; sacc[mt][j][2] = 0; sacc[mt][j][3] = 0; }
#pragma unroll
            for (int kc = 0; kc < 4; ++kc) {
                u32 bh[4];
                ldsm4(bh, sbase + koff[kc] + coff);
                mma16816(sacc[0][0], qf[0][kc], bh[0], bh[1]);
                mma16816(sacc[0][1], qf[0][kc], bh[2], bh[3]);
                mma16816(sacc[1][0], qf[1][kc], bh[0], bh[1]);
                mma16816(sacc[1][1], qf[1][kc], bh[2], bh[3]);
            }

            // ---- softmax (exp only) -> A fragments ----
            u32 Ah[2][4];
#pragma unroll
            for (int mt = 0; mt < 2; ++mt)
#pragma unroll
                for (int j = 0; j < 2; ++j) {
                    float p0 = ex2f(sacc[mt][j][0]);
                    float p1 = ex2f(sacc[mt][j][1]);
                    float p2 = ex2f(sacc[mt][j][2]);
                    float p3 = ex2f(sacc[mt][j][3]);
                    Ah[mt][2 * j]     = packh2(p0, p1);
                    Ah[mt][2 * j + 1] = packh2(p2, p3);
                }

            // ---- rowsum via km-column MMA ----
            {
                u32 bm[2];
                ldsm2t(bm, sbase + moff0 + (u32)c * 256);
                mma16816(oaccE[0], Ah[0], bm[0], bm[1]);
                mma16816(oaccE[1], Ah[1], bm[0], bm[1]);
            }

            // ---- GEMM2 chunk: O += P @ (km*V) ----
#pragma unroll
            for (int j2 = 0; j2 < 4; ++j2) {
                u32 vh[4];
                ldsm4t(vh, sbase + voff[j2] + coff);
                mma16816(oacc[0][2 * j2],     Ah[0], vh[0], vh[1]);
                mma16816(oacc[0][2 * j2 + 1], Ah[0], vh[2], vh[3]);
                mma16816(oacc[1][2 * j2],     Ah[1], vh[0], vh[1]);
                mma16816(oacc[1][2 * j2 + 1], Ah[1], vh[2], vh[3]);
            }
        }

        if (L == 0) mbar_arrive(smb + SM_BAR + 32 + s * 8);

        if (tid == 0 && kt + 3 < NTILES) {
            const int it = kt + 3;
            u32 s2 = (u32)it & 3;
            u32 fb = smb + SM_BAR + s2 * 8;
            mbar_wait(smb + SM_BAR + 32 + s2 * 8, ((((u32)it >> 2) & 1u) ^ 1u));
            mbar_expect_tx(fb, (u32)TILEB);
            bulk_cp(smb + s2 * STAGESZ, g_kv[b][it], (u32)TILEB, fb);
        }
    }

    // ---- epilogue: rowsum from extra tile, 2-way key-half combine ----
    float rsA[2], rsB[2];
#pragma unroll
    for (int mt = 0; mt < 2; ++mt) {
        rsA[mt] = __shfl_sync(0xFFFFFFFFu, oaccE[mt][0], L & ~3);
        rsB[mt] = __shfl_sync(0xFFFFFFFFu, oaccE[mt][2], L & ~3);
    }
    __syncthreads();   // pipeline drained; stage smem reusable

    float* OS = reinterpret_cast<float*>(sm);            // [128][64] f32 = 32KB
    float* RS = reinterpret_cast<float*>(sm + 32768);    // [128]
    if (kh == 1) {
#pragma unroll
        for (int mt = 0; mt < 2; ++mt) {
            int ra = mg * 32 + mt * 16 + (L >> 2);
            int rb = ra + 8;
#pragma unroll
            for (int j = 0; j < 8; ++j) {
                *reinterpret_cast<float2*>(&OS[ra * 64 + 8 * j + 2 * (L & 3)]) =
                    make_float2(oacc[mt][j][0], oacc[mt][j][1]);
                *reinterpret_cast<float2*>(&OS[rb * 64 + 8 * j + 2 * (L & 3)]) =
                    make_float2(oacc[mt][j][2], oacc[mt][j][3]);
            }
            if ((L & 3) == 0) { RS[ra] = rsA[mt]; RS[rb] = rsB[mt]; }
        }
    }
    __syncthreads();
    if (kh == 0) {
#pragma unroll
        for (int mt = 0; mt < 2; ++mt) {
            int ra = mg * 32 + mt * 16 + (L >> 2);
            int rb = ra + 8;
            float sa = rsA[mt] + RS[ra];
            float sb = rsB[mt] + RS[rb];
            float dva = QM[b * Ll + q0 + ra] / fmaxf(sa, 2e-15f);
            float dvb = QM[b * Ll + q0 + rb] / fmaxf(sb, 2e-15f);
            float* oa = Out + (size_t)(b * Ll + q0 + ra) * Dd + 2 * (L & 3);
            float* ob = Out + (size_t)(b * Ll + q0 + rb) * Dd + 2 * (L & 3);
#pragma unroll
            for (int j = 0; j < 8; ++j) {
                int ca = ra * 64 + 8 * j + 2 * (L & 3);
                int cb = rb * 64 + 8 * j + 2 * (L & 3);
                float2 ua = *reinterpret_cast<const float2*>(&OS[ca]);
                float2 ub = *reinterpret_cast<const float2*>(&OS[cb]);
                *reinterpret_cast<float2*>(oa + 8 * j) =
                    make_float2((oacc[mt][j][0] + ua.x) * dva,
                                (oacc[mt][j][1] + ua.y) * dva);
                *reinterpret_cast<float2*>(ob + 8 * j) =
                    make_float2((oacc[mt][j][2] + ub.x) * dvb,
                                (oacc[mt][j][3] + ub.y) * dvb);
            }
        }
    }
}

extern "C" void kernel_launch(void* const* d_in, const int* in_sizes, int n_in,
                              void* d_out, int out_size) {
    const float* Q  = (const float*)d_in[0];
    const float* K  = (const float*)d_in[1];
    const float* V  = (const float*)d_in[2];
    const float* QM = (const float*)d_in[3];
    const float* KM = (const float*)d_in[4];
    float* Out = (float*)d_out;

    presplit<<<dim3(512, 3), 256>>>(Q, K, V, KM);

    cudaFuncSetAttribute(attn_mma, cudaFuncAttributeMaxDynamicSharedMemorySize, SM_TOT);
    dim3 grid(Ll / TQ, Bb);   // 16 q-tiles x 8 batches = 128 CTAs, 1 per SM
    attn_mma<<<grid, NT, SM_TOT>>>(QM, Out);
}